// round 2
// baseline (speedup 1.0000x reference)
#include <cuda_runtime.h>
#include <cstdint>

// Problem constants (fixed shapes)
#define Tn 100
#define Bn 4096
#define Cn 512
#define Dn 512
#define NW 16                    // 512 bits / 32 = mask words per (t,b)

// ---------------- scratch (static device globals; no allocation) ------------
__device__ uint32_t g_mask[Tn*Bn*NW];   // 26.2 MB packed dropout masks
__device__ float    g_invn[Bn*Tn];      // 1/|y_tb|
__device__ float    g_u[Bn*Cn];         // u_b[c] = 2 x_bc * sum_t m/n
__device__ float    g_sigma[Bn];        // sum_t 1/n
__device__ float    g_S[Bn*Dn];         // sum_t f_t  (unnormalized mean dir)
__device__ float    g_v[Bn*Cn];         // v_b = W^T S_b
__device__ float    g_sinv[Bn];         // 1/|S_b|
__device__ float    g_c0[Bn];           // b^T S_b

// ---------------- threefry2x32 (JAX-exact, key = (0, 42)) -------------------
__device__ __forceinline__ void tf_round4(uint32_t& x0, uint32_t& x1,
                                          int a, int b, int c, int d) {
  x0 += x1; x1 = __funnelshift_l(x1, x1, a); x1 ^= x0;
  x0 += x1; x1 = __funnelshift_l(x1, x1, b); x1 ^= x0;
  x0 += x1; x1 = __funnelshift_l(x1, x1, c); x1 ^= x0;
  x0 += x1; x1 = __funnelshift_l(x1, x1, d); x1 ^= x0;
}

__device__ __forceinline__ uint2 threefry2x32(uint32_t x0, uint32_t x1) {
  const uint32_t k0 = 0u, k1 = 42u;
  const uint32_t k2 = k0 ^ k1 ^ 0x1BD11BDAu;
  x0 += k0; x1 += k1;
  tf_round4(x0, x1, 13, 15, 26, 6);   x0 += k1; x1 += k2 + 1u;
  tf_round4(x0, x1, 17, 29, 16, 24);  x0 += k2; x1 += k0 + 2u;
  tf_round4(x0, x1, 13, 15, 26, 6);   x0 += k0; x1 += k1 + 3u;
  tf_round4(x0, x1, 17, 29, 16, 24);  x0 += k1; x1 += k2 + 4u;
  tf_round4(x0, x1, 13, 15, 26, 6);   x0 += k2; x1 += k0 + 5u;
  return make_uint2(x0, x1);
}

// K0: JAX threefry_partitionable 32-bit draws.
// Element i gets counter (hi32(i)=0, lo32(i)=i); bits(i) = out.x ^ out.y.
// uniform < 0.5  <=>  bit31(bits) == 0  => keep.
// One thread per element; warp ballot packs 32 keep-bits into one mask word
// (ballot bit k == lane k == element base+k, matching g_mask bit layout).
__global__ void k0_masks() {
  uint32_t i = blockIdx.x * blockDim.x + threadIdx.x;   // element index
  uint2 o = threefry2x32(0u, i);
  uint32_t keep = (((o.x ^ o.y) >> 31) & 1u) ^ 1u;
  uint32_t word = __ballot_sync(0xFFFFFFFFu, keep != 0u);
  if ((threadIdx.x & 31u) == 0u) g_mask[i >> 5] = word;
}

// K1: per-b block; full [100 x 512] GEMM y = 2 W (x*m) + bias, keep only the
// per-(t) squared row norms. 320 threads = 20 tq x 16 dq, micro-tile 5t x 4d.
__global__ __launch_bounds__(320) void k1_norms(
    const float* __restrict__ x, const float* __restrict__ W,
    const float* __restrict__ bias) {
  __shared__ float xs[Cn];            //  2.0 KB : 2*x_b
  __shared__ float Ws[64][65];        // 16.6 KB : W tile, [c][d], padded
  __shared__ float xd[64][100];       // 25.6 KB : expanded 2*x*m, [c][t]
  __shared__ float norm2[112];        //  0.4 KB : per-t |y|^2 accumulators
  const int b = blockIdx.x;
  const int tid = threadIdx.x;

  for (int c = tid; c < Cn; c += 320) xs[c] = 2.0f * x[b * Cn + c];
  if (tid < 112) norm2[tid] = 0.0f;

  const int dq = tid & 15;
  const int tq = tid >> 4;
  const int t0 = tq * 5;
  const int d_in = dq * 4;

  for (int dt = 0; dt < 8; dt++) {
    float acc[5][4];
#pragma unroll
    for (int j = 0; j < 5; j++)
#pragma unroll
      for (int i = 0; i < 4; i++) acc[j][i] = 0.0f;
    const int dbase = dt * 64;

    for (int kt = 0; kt < 8; kt++) {
      const int cbase = kt * 64;
      __syncthreads();
      // stage W[dbase+d][cbase+c] -> Ws[c][d]  (coalesced over c)
      for (int l = tid; l < 4096; l += 320) {
        int d = l >> 6, c = l & 63;
        Ws[c][d] = W[(dbase + d) * Cn + cbase + c];
      }
      // expand dropout-masked input: xd[c][t] = m ? 2*x : 0
      for (int l = tid; l < 6400; l += 320) {
        int c = l / 100;
        int t = l - c * 100;
        int cg = cbase + c;
        uint32_t mw = g_mask[(t * Bn + b) * NW + (cg >> 5)];
        xd[c][t] = ((mw >> (cg & 31)) & 1u) ? xs[cg] : 0.0f;
      }
      __syncthreads();
#pragma unroll 4
      for (int c = 0; c < 64; c++) {
        float w0 = Ws[c][d_in + 0];
        float w1 = Ws[c][d_in + 1];
        float w2 = Ws[c][d_in + 2];
        float w3 = Ws[c][d_in + 3];
#pragma unroll
        for (int j = 0; j < 5; j++) {
          float xv = xd[c][t0 + j];
          acc[j][0] = fmaf(xv, w0, acc[j][0]);
          acc[j][1] = fmaf(xv, w1, acc[j][1]);
          acc[j][2] = fmaf(xv, w2, acc[j][2]);
          acc[j][3] = fmaf(xv, w3, acc[j][3]);
        }
      }
    }
    // add bias, square, reduce into per-t accumulators
    float bb0 = bias[dbase + d_in + 0];
    float bb1 = bias[dbase + d_in + 1];
    float bb2 = bias[dbase + d_in + 2];
    float bb3 = bias[dbase + d_in + 3];
#pragma unroll
    for (int j = 0; j < 5; j++) {
      float y0 = acc[j][0] + bb0;
      float y1 = acc[j][1] + bb1;
      float y2 = acc[j][2] + bb2;
      float y3 = acc[j][3] + bb3;
      float s = y0 * y0 + y1 * y1 + y2 * y2 + y3 * y3;
      atomicAdd(&norm2[t0 + j], s);
    }
  }
  __syncthreads();
  if (tid < Tn) g_invn[b * Tn + tid] = rsqrtf(norm2[tid]);
}

// K2: u_b[c] = 2 x_bc * sum_t m_tbc / n_tb ;  sigma_b = sum_t 1/n_tb
__global__ void k2_u(const float* __restrict__ x) {
  __shared__ float invn_s[Tn];
  const int b = blockIdx.x, tid = threadIdx.x;  // 128 threads
  if (tid < Tn) invn_s[tid] = g_invn[b * Tn + tid];
  __syncthreads();
  if (tid == 0) {
    float s = 0.0f;
    for (int t = 0; t < Tn; t++) s += invn_s[t];
    g_sigma[b] = s;
  }
  for (int c = tid; c < Cn; c += 128) {
    int w = c >> 5, sh = c & 31;
    float s = 0.0f;
    for (int t = 0; t < Tn; t++)
      if ((g_mask[(t * Bn + b) * NW + w] >> sh) & 1u) s += invn_s[t];
    g_u[b * Cn + c] = 2.0f * x[b * Cn + c] * s;
  }
}

// K3: small GEMMs. MODE 0: S = u * W^T + sigma*bias  ([B,C]x[C,D])
//                  MODE 1: v = S * W                 ([B,D]x[D,C])
template <int MODE>
__global__ void k3_gemm(const float* __restrict__ Wm,
                        const float* __restrict__ bias) {
  __shared__ float As[64][65];
  __shared__ float Bs[64][65];
  const float* A = (MODE == 0) ? g_u : g_S;
  float* outp = (MODE == 0) ? g_S : g_v;
  const int n0 = blockIdx.x * 64, m0 = blockIdx.y * 64;
  const int tid = threadIdx.x;                // 256
  const int nq = tid & 15, mq = tid >> 4;
  float acc[4][4] = {};
  for (int k0 = 0; k0 < 512; k0 += 64) {
    __syncthreads();
    for (int l = tid; l < 4096; l += 256) {
      int mm = l >> 6, kk = l & 63;
      As[kk][mm] = A[(m0 + mm) * 512 + k0 + kk];
    }
    if (MODE == 0) {  // B(k,n) = W[n][k], coalesced over k
      for (int l = tid; l < 4096; l += 256) {
        int nn = l >> 6, kk = l & 63;
        Bs[kk][nn] = Wm[(n0 + nn) * 512 + k0 + kk];
      }
    } else {          // B(k,n) = W[k][n], coalesced over n
      for (int l = tid; l < 4096; l += 256) {
        int kk = l >> 6, nn = l & 63;
        Bs[kk][nn] = Wm[(k0 + kk) * 512 + n0 + nn];
      }
    }
    __syncthreads();
#pragma unroll 8
    for (int kk = 0; kk < 64; kk++) {
      float a[4], bb[4];
#pragma unroll
      for (int i = 0; i < 4; i++) { a[i] = As[kk][mq * 4 + i]; bb[i] = Bs[kk][nq * 4 + i]; }
#pragma unroll
      for (int i = 0; i < 4; i++)
#pragma unroll
        for (int j = 0; j < 4; j++) acc[i][j] = fmaf(a[i], bb[j], acc[i][j]);
    }
  }
#pragma unroll
  for (int i = 0; i < 4; i++) {
    int m = m0 + mq * 4 + i;
    float sg = (MODE == 0) ? g_sigma[m] : 0.0f;
#pragma unroll
    for (int j = 0; j < 4; j++) {
      int n = n0 + nq * 4 + j;
      float v = acc[i][j];
      if (MODE == 0) v += sg * bias[n];
      outp[m * 512 + n] = v;
    }
  }
}

// K3c: 1/|S_b| and b^T S_b
__global__ void k3c_reduce(const float* __restrict__ bias) {
  __shared__ float r1[128], r2[128];
  const int b = blockIdx.x, tid = threadIdx.x;  // 128
  float s1 = 0.0f, s2 = 0.0f;
  for (int d = tid; d < Dn; d += 128) {
    float v = g_S[b * Dn + d];
    s1 += v * v;
    s2 += bias[d] * v;
  }
  r1[tid] = s1; r2[tid] = s2;
  __syncthreads();
  for (int o = 64; o > 0; o >>= 1) {
    if (tid < o) { r1[tid] += r1[tid + o]; r2[tid] += r2[tid + o]; }
    __syncthreads();
  }
  if (tid == 0) { g_sinv[b] = rsqrtf(r1[0]); g_c0[b] = r2[0]; }
}

// K4: score_tb = (2 sum_c m*x*v + c0) * invn * sinv ; out = std over t (ddof=0)
__global__ void k4_scores(const float* __restrict__ x, float* __restrict__ out) {
  __shared__ float xv[Cn];
  __shared__ float sc[Tn];
  const int b = blockIdx.x, tid = threadIdx.x;  // 128
  for (int c = tid; c < Cn; c += 128)
    xv[c] = 2.0f * x[b * Cn + c] * g_v[b * Cn + c];
  __syncthreads();
  if (tid < Tn) {
    const int t = tid;
    const uint32_t* mw = &g_mask[(t * Bn + b) * NW];
    float s = 0.0f;
#pragma unroll
    for (int w = 0; w < NW; w++) {
      uint32_t m = mw[w];
      int base = w * 32;
#pragma unroll
      for (int k = 0; k < 32; k++)
        if (m & (1u << k)) s += xv[base + k];
    }
    sc[t] = (s + g_c0[b]) * g_invn[b * Tn + t] * g_sinv[b];
  }
  __syncthreads();
  if (tid == 0) {
    float m = 0.0f;
    for (int t = 0; t < Tn; t++) m += sc[t];
    m *= (1.0f / Tn);
    float v = 0.0f;
    for (int t = 0; t < Tn; t++) { float d = sc[t] - m; v += d * d; }
    v *= (1.0f / Tn);
    out[b] = sqrtf(v);
  }
}

extern "C" void kernel_launch(void* const* d_in, const int* in_sizes, int n_in,
                              void* d_out, int out_size) {
  const float* x    = (const float*)d_in[0];
  const float* W    = (const float*)d_in[1];
  const float* bias = (const float*)d_in[2];
  float* out = (float*)d_out;

  k0_masks<<<819200, 256>>>();                // Tn*Bn*Cn / 256 elements
  k1_norms<<<Bn, 320>>>(x, W, bias);
  k2_u<<<Bn, 128>>>(x);
  k3_gemm<0><<<dim3(8, 64), 256>>>(W, bias);  // S
  k3c_reduce<<<Bn, 128>>>(bias);              // |S|, b^T S
  k3_gemm<1><<<dim3(8, 64), 256>>>(W, bias);  // v = W^T S
  k4_scores<<<Bn, 128>>>(x, out);
}

// round 3
// speedup vs baseline: 4.9998x; 4.9998x over previous
#include <cuda_runtime.h>
#include <cstdint>

// Problem constants (fixed shapes)
#define Tn 100
#define Bn 4096
#define Cn 512
#define Dn 512
#define NW 16                    // 512 bits / 32 = mask words per (t,b)

// ---------------- scratch (static device globals; no allocation) ------------
__device__ uint32_t g_mask[Tn*Bn*NW];   // 26.2 MB packed dropout masks
__device__ float    g_invn[Bn*Tn];      // 1/|y_tb|
__device__ float    g_u[Bn*Cn];         // u_b[c] = 2 x_bc * sum_t m/n
__device__ float    g_sigma[Bn];        // sum_t 1/n
__device__ float    g_S[Bn*Dn];         // sum_t f_t  (unnormalized mean dir)
__device__ float    g_v[Bn*Cn];         // v_b = W^T S_b
__device__ float    g_sinv[Bn];         // 1/|S_b|
__device__ float    g_c0[Bn];           // b^T S_b

// ---------------- threefry2x32 (JAX-exact, key = (0, 42)) -------------------
__device__ __forceinline__ void tf_round4(uint32_t& x0, uint32_t& x1,
                                          int a, int b, int c, int d) {
  x0 += x1; x1 = __funnelshift_l(x1, x1, a); x1 ^= x0;
  x0 += x1; x1 = __funnelshift_l(x1, x1, b); x1 ^= x0;
  x0 += x1; x1 = __funnelshift_l(x1, x1, c); x1 ^= x0;
  x0 += x1; x1 = __funnelshift_l(x1, x1, d); x1 ^= x0;
}

__device__ __forceinline__ uint2 threefry2x32(uint32_t x0, uint32_t x1) {
  const uint32_t k0 = 0u, k1 = 42u;
  const uint32_t k2 = k0 ^ k1 ^ 0x1BD11BDAu;
  x0 += k0; x1 += k1;
  tf_round4(x0, x1, 13, 15, 26, 6);   x0 += k1; x1 += k2 + 1u;
  tf_round4(x0, x1, 17, 29, 16, 24);  x0 += k2; x1 += k0 + 2u;
  tf_round4(x0, x1, 13, 15, 26, 6);   x0 += k0; x1 += k1 + 3u;
  tf_round4(x0, x1, 17, 29, 16, 24);  x0 += k1; x1 += k2 + 4u;
  tf_round4(x0, x1, 13, 15, 26, 6);   x0 += k2; x1 += k0 + 5u;
  return make_uint2(x0, x1);
}

// K0: JAX threefry_partitionable 32-bit draws. bits(i) = out.x ^ out.y of
// threefry2x32(key=(0,42), ctr=(0, i)); keep <=> bit31 == 0.
__global__ void k0_masks() {
  uint32_t i = blockIdx.x * blockDim.x + threadIdx.x;   // element index
  uint2 o = threefry2x32(0u, i);
  uint32_t keep = (((o.x ^ o.y) >> 31) & 1u) ^ 1u;
  uint32_t word = __ballot_sync(0xFFFFFFFFu, keep != 0u);
  if ((threadIdx.x & 31u) == 0u) g_mask[i >> 5] = word;
}

// ---------------- K1: tf32 tensor-core row-norm GEMM ------------------------
// Per block = one b. Compute Yt[D=512, T=112] = W[D,C] x Z^T[C,T] with
// mma.sync.m16n8k8 tf32; Z[t][c] = mask ? 2*x[c] : 0 built in-register.
// Only per-t squared norms survive. 8 warps = 4 (m: 32 d each) x 2 (n: 56 t).
__device__ __forceinline__ uint32_t f2tf32(float v) {
  uint32_t r; asm("cvt.rna.tf32.f32 %0, %1;" : "=r"(r) : "f"(v));
  return r;
}

__device__ __forceinline__ void mma_tf32(float (&d)[4],
                                         uint32_t a0, uint32_t a1,
                                         uint32_t a2, uint32_t a3,
                                         uint32_t b0, uint32_t b1) {
  asm volatile(
      "mma.sync.aligned.m16n8k8.row.col.f32.tf32.tf32.f32 "
      "{%0,%1,%2,%3}, {%4,%5,%6,%7}, {%8,%9}, {%0,%1,%2,%3};"
      : "+f"(d[0]), "+f"(d[1]), "+f"(d[2]), "+f"(d[3])
      : "r"(a0), "r"(a1), "r"(a2), "r"(a3), "r"(b0), "r"(b1));
}

#define WPAD 68   // Ws row stride in floats (68 mod 32 = 4 -> conflict-free frags)

__global__ __launch_bounds__(256) void k1_norms_tc(
    const float* __restrict__ x, const float* __restrict__ W,
    const float* __restrict__ bias) {
  __shared__ float    xs[Cn];          //  2 KB : tf32(2*x)
  __shared__ uint32_t maskS[112 * NW]; //  7 KB : mask words, t>=100 zeroed
  __shared__ float    Ws[128 * WPAD];  // 34.8 KB : tf32 W tile [128 d][64 c]
  __shared__ float    norm2[112];
  const int b = blockIdx.x;
  const int tid = threadIdx.x;
  const int lane = tid & 31, wid = tid >> 5;
  const int warp_m = wid & 3;          // 4 m-warps (32 d each)
  const int warp_n = wid >> 2;         // 2 n-warps (56 t each)
  const int gID = lane >> 2, tig = lane & 3;
  const int n0 = warp_n * 56;

  for (int c = tid; c < Cn; c += 256)
    xs[c] = __uint_as_float(f2tf32(2.0f * x[b * Cn + c]));
  for (int i = tid; i < 112 * NW; i += 256) {
    int t = i >> 4, w = i & 15;
    maskS[i] = (t < Tn) ? g_mask[(t * Bn + b) * NW + w] : 0u;
  }
  if (tid < 112) norm2[tid] = 0.0f;

  for (int mi = 0; mi < 4; mi++) {     // 128-d chunk
    float acc[2][7][4];
#pragma unroll
    for (int mt = 0; mt < 2; mt++)
#pragma unroll
      for (int nt = 0; nt < 7; nt++)
#pragma unroll
        for (int r = 0; r < 4; r++) acc[mt][nt][r] = 0.0f;

    for (int kc = 0; kc < 8; kc++) {   // 64-c chunk
      __syncthreads();
      {  // stage W[mi*128 + d][kc*64 + c] -> Ws[d][c], tf32, pad WPAD
        const float* Wg = W + (mi * 128) * Cn + kc * 64;
        for (int l = tid; l < 2048; l += 256) {
          int d = l >> 4, c4 = (l & 15) << 2;
          float4 v = *reinterpret_cast<const float4*>(Wg + d * Cn + c4);
          float4 o;
          o.x = __uint_as_float(f2tf32(v.x));
          o.y = __uint_as_float(f2tf32(v.y));
          o.z = __uint_as_float(f2tf32(v.z));
          o.w = __uint_as_float(f2tf32(v.w));
          *reinterpret_cast<float4*>(&Ws[d * WPAD + c4]) = o;
        }
      }
      __syncthreads();

      // hoist this kc's two mask words per n-tile
      uint32_t mwa[7], mwb[7];
#pragma unroll
      for (int nt = 0; nt < 7; nt++) {
        int t = n0 + nt * 8 + gID;
        mwa[nt] = maskS[t * NW + kc * 2];
        mwb[nt] = maskS[t * NW + kc * 2 + 1];
      }

#pragma unroll
      for (int kt = 0; kt < 8; kt++) { // k8 tiles
        const int cl = kt * 8 + tig;
        uint32_t xv0 = __float_as_uint(xs[kc * 64 + cl]);
        uint32_t xv1 = __float_as_uint(xs[kc * 64 + cl + 4]);
        // A fragments for warp's two m16 tiles (d rows in Ws local coords)
        const int r0 = (warp_m * 32 + gID) * WPAD + cl;
        uint32_t a00 = __float_as_uint(Ws[r0]);
        uint32_t a01 = __float_as_uint(Ws[r0 + 8 * WPAD]);
        uint32_t a02 = __float_as_uint(Ws[r0 + 4]);
        uint32_t a03 = __float_as_uint(Ws[r0 + 8 * WPAD + 4]);
        uint32_t a10 = __float_as_uint(Ws[r0 + 16 * WPAD]);
        uint32_t a11 = __float_as_uint(Ws[r0 + 24 * WPAD]);
        uint32_t a12 = __float_as_uint(Ws[r0 + 16 * WPAD + 4]);
        uint32_t a13 = __float_as_uint(Ws[r0 + 24 * WPAD + 4]);
        const int bit = ((kt & 3) << 3) + tig;
#pragma unroll
        for (int nt = 0; nt < 7; nt++) {
          uint32_t w = (kt < 4) ? mwa[nt] : mwb[nt];
          uint32_t b0 = ((w >> bit) & 1u) ? xv0 : 0u;
          uint32_t b1 = ((w >> (bit + 4)) & 1u) ? xv1 : 0u;
          mma_tf32(acc[0][nt], a00, a01, a02, a03, b0, b1);
          mma_tf32(acc[1][nt], a10, a11, a12, a13, b0, b1);
        }
      }
    }

    // fold this 128-d chunk into per-t norms
    const int dg = mi * 128 + warp_m * 32 + gID;
    float bi00 = bias[dg],      bi01 = bias[dg + 8];
    float bi10 = bias[dg + 16], bi11 = bias[dg + 24];
#pragma unroll
    for (int nt = 0; nt < 7; nt++) {
      int t = n0 + nt * 8 + 2 * tig;
      float y00 = acc[0][nt][0] + bi00, y01 = acc[0][nt][1] + bi00;
      float y02 = acc[0][nt][2] + bi01, y03 = acc[0][nt][3] + bi01;
      float y10 = acc[1][nt][0] + bi10, y11 = acc[1][nt][1] + bi10;
      float y12 = acc[1][nt][2] + bi11, y13 = acc[1][nt][3] + bi11;
      float pt  = y00 * y00 + y02 * y02 + y10 * y10 + y12 * y12;
      float pt1 = y01 * y01 + y03 * y03 + y11 * y11 + y13 * y13;
      atomicAdd(&norm2[t], pt);
      atomicAdd(&norm2[t + 1], pt1);
    }
  }
  __syncthreads();
  if (tid < Tn) g_invn[b * Tn + tid] = rsqrtf(norm2[tid]);
}

// K2: u_b[c] = 2 x_bc * sum_t m_tbc / n_tb ;  sigma_b = sum_t 1/n_tb
__global__ void k2_u(const float* __restrict__ x) {
  __shared__ float invn_s[Tn];
  const int b = blockIdx.x, tid = threadIdx.x;  // 128 threads
  if (tid < Tn) invn_s[tid] = g_invn[b * Tn + tid];
  __syncthreads();
  if (tid == 0) {
    float s = 0.0f;
    for (int t = 0; t < Tn; t++) s += invn_s[t];
    g_sigma[b] = s;
  }
  for (int c = tid; c < Cn; c += 128) {
    int w = c >> 5, sh = c & 31;
    float s = 0.0f;
    for (int t = 0; t < Tn; t++)
      if ((g_mask[(t * Bn + b) * NW + w] >> sh) & 1u) s += invn_s[t];
    g_u[b * Cn + c] = 2.0f * x[b * Cn + c] * s;
  }
}

// K3: small GEMMs. MODE 0: S = u * W^T + sigma*bias  ([B,C]x[C,D])
//                  MODE 1: v = S * W                 ([B,D]x[D,C])
template <int MODE>
__global__ void k3_gemm(const float* __restrict__ Wm,
                        const float* __restrict__ bias) {
  __shared__ float As[64][65];
  __shared__ float Bs[64][65];
  const float* A = (MODE == 0) ? g_u : g_S;
  float* outp = (MODE == 0) ? g_S : g_v;
  const int n0 = blockIdx.x * 64, m0 = blockIdx.y * 64;
  const int tid = threadIdx.x;                // 256
  const int nq = tid & 15, mq = tid >> 4;
  float acc[4][4] = {};
  for (int k0 = 0; k0 < 512; k0 += 64) {
    __syncthreads();
    for (int l = tid; l < 4096; l += 256) {
      int mm = l >> 6, kk = l & 63;
      As[kk][mm] = A[(m0 + mm) * 512 + k0 + kk];
    }
    if (MODE == 0) {
      for (int l = tid; l < 4096; l += 256) {
        int nn = l >> 6, kk = l & 63;
        Bs[kk][nn] = Wm[(n0 + nn) * 512 + k0 + kk];
      }
    } else {
      for (int l = tid; l < 4096; l += 256) {
        int kk = l >> 6, nn = l & 63;
        Bs[kk][nn] = Wm[(k0 + kk) * 512 + n0 + nn];
      }
    }
    __syncthreads();
#pragma unroll 8
    for (int kk = 0; kk < 64; kk++) {
      float a[4], bb[4];
#pragma unroll
      for (int i = 0; i < 4; i++) { a[i] = As[kk][mq * 4 + i]; bb[i] = Bs[kk][nq * 4 + i]; }
#pragma unroll
      for (int i = 0; i < 4; i++)
#pragma unroll
        for (int j = 0; j < 4; j++) acc[i][j] = fmaf(a[i], bb[j], acc[i][j]);
    }
  }
#pragma unroll
  for (int i = 0; i < 4; i++) {
    int m = m0 + mq * 4 + i;
    float sg = (MODE == 0) ? g_sigma[m] : 0.0f;
#pragma unroll
    for (int j = 0; j < 4; j++) {
      int n = n0 + nq * 4 + j;
      float v = acc[i][j];
      if (MODE == 0) v += sg * bias[n];
      outp[m * 512 + n] = v;
    }
  }
}

// K3c: 1/|S_b| and b^T S_b
__global__ void k3c_reduce(const float* __restrict__ bias) {
  __shared__ float r1[128], r2[128];
  const int b = blockIdx.x, tid = threadIdx.x;  // 128
  float s1 = 0.0f, s2 = 0.0f;
  for (int d = tid; d < Dn; d += 128) {
    float v = g_S[b * Dn + d];
    s1 += v * v;
    s2 += bias[d] * v;
  }
  r1[tid] = s1; r2[tid] = s2;
  __syncthreads();
  for (int o = 64; o > 0; o >>= 1) {
    if (tid < o) { r1[tid] += r1[tid + o]; r2[tid] += r2[tid + o]; }
    __syncthreads();
  }
  if (tid == 0) { g_sinv[b] = rsqrtf(r1[0]); g_c0[b] = r2[0]; }
}

// K4: score_tb = (2 sum_c m*x*v + c0) * invn * sinv ; out = std over t (ddof=0)
__global__ void k4_scores(const float* __restrict__ x, float* __restrict__ out) {
  __shared__ float xv[Cn];
  __shared__ float sc[Tn];
  const int b = blockIdx.x, tid = threadIdx.x;  // 128
  for (int c = tid; c < Cn; c += 128)
    xv[c] = 2.0f * x[b * Cn + c] * g_v[b * Cn + c];
  __syncthreads();
  if (tid < Tn) {
    const int t = tid;
    const uint32_t* mw = &g_mask[(t * Bn + b) * NW];
    float s = 0.0f;
#pragma unroll
    for (int w = 0; w < NW; w++) {
      uint32_t m = mw[w];
      int base = w * 32;
#pragma unroll
      for (int k = 0; k < 32; k++)
        if (m & (1u << k)) s += xv[base + k];
    }
    sc[t] = (s + g_c0[b]) * g_invn[b * Tn + t] * g_sinv[b];
  }
  __syncthreads();
  if (tid == 0) {
    float m = 0.0f;
    for (int t = 0; t < Tn; t++) m += sc[t];
    m *= (1.0f / Tn);
    float v = 0.0f;
    for (int t = 0; t < Tn; t++) { float d = sc[t] - m; v += d * d; }
    v *= (1.0f / Tn);
    out[b] = sqrtf(v);
  }
}

extern "C" void kernel_launch(void* const* d_in, const int* in_sizes, int n_in,
                              void* d_out, int out_size) {
  const float* x    = (const float*)d_in[0];
  const float* W    = (const float*)d_in[1];
  const float* bias = (const float*)d_in[2];
  float* out = (float*)d_out;

  k0_masks<<<819200, 256>>>();                // Tn*Bn*Cn / 256 elements
  k1_norms_tc<<<Bn, 256>>>(x, W, bias);
  k2_u<<<Bn, 128>>>(x);
  k3_gemm<0><<<dim3(8, 64), 256>>>(W, bias);  // S
  k3c_reduce<<<Bn, 128>>>(bias);              // |S|, b^T S
  k3_gemm<1><<<dim3(8, 64), 256>>>(W, bias);  // v = W^T S
  k4_scores<<<Bn, 128>>>(x, out);
}

// round 4
// speedup vs baseline: 6.3959x; 1.2792x over previous
#include <cuda_runtime.h>
#include <cstdint>

// Problem constants (fixed shapes)
#define Tn 100
#define Bn 4096
#define Cn 512
#define Dn 512
#define NW 16                    // 512 bits / 32 = mask words per (t,b)

// ---------------- scratch (static device globals; no allocation) ------------
__device__ uint32_t g_mask[Tn*Bn*NW];   // 26.2 MB packed dropout masks
__device__ float    g_invn[Bn*Tn];      // 1/|y_tb|
__device__ float    g_u[Bn*Cn];         // u_b[c] = 2 x_bc * sum_t m/n
__device__ float    g_sigma[Bn];        // sum_t 1/n
__device__ float    g_S[Bn*Dn];         // sum_t f_t  (unnormalized mean dir)
__device__ float    g_v[Bn*Cn];         // v_b = W^T S_b
__device__ float    g_sinv[Bn];         // 1/|S_b|
__device__ float    g_c0[Bn];           // b^T S_b

// ---------------- threefry2x32 (JAX-exact, key = (0, 42)) -------------------
__device__ __forceinline__ void tf_round4(uint32_t& x0, uint32_t& x1,
                                          int a, int b, int c, int d) {
  x0 += x1; x1 = __funnelshift_l(x1, x1, a); x1 ^= x0;
  x0 += x1; x1 = __funnelshift_l(x1, x1, b); x1 ^= x0;
  x0 += x1; x1 = __funnelshift_l(x1, x1, c); x1 ^= x0;
  x0 += x1; x1 = __funnelshift_l(x1, x1, d); x1 ^= x0;
}

__device__ __forceinline__ uint2 threefry2x32(uint32_t x0, uint32_t x1) {
  const uint32_t k0 = 0u, k1 = 42u;
  const uint32_t k2 = k0 ^ k1 ^ 0x1BD11BDAu;
  x0 += k0; x1 += k1;
  tf_round4(x0, x1, 13, 15, 26, 6);   x0 += k1; x1 += k2 + 1u;
  tf_round4(x0, x1, 17, 29, 16, 24);  x0 += k2; x1 += k0 + 2u;
  tf_round4(x0, x1, 13, 15, 26, 6);   x0 += k0; x1 += k1 + 3u;
  tf_round4(x0, x1, 17, 29, 16, 24);  x0 += k1; x1 += k2 + 4u;
  tf_round4(x0, x1, 13, 15, 26, 6);   x0 += k2; x1 += k0 + 5u;
  return make_uint2(x0, x1);
}

// K0: JAX threefry_partitionable 32-bit draws. bits(i) = out.x ^ out.y of
// threefry2x32(key=(0,42), ctr=(0, i)); keep <=> bit31 == 0.
__global__ void k0_masks() {
  uint32_t i = blockIdx.x * blockDim.x + threadIdx.x;   // element index
  uint2 o = threefry2x32(0u, i);
  uint32_t keep = (((o.x ^ o.y) >> 31) & 1u) ^ 1u;
  uint32_t word = __ballot_sync(0xFFFFFFFFu, keep != 0u);
  if ((threadIdx.x & 31u) == 0u) g_mask[i >> 5] = word;
}

// ---------------- K1: tf32 tensor-core row-norm GEMM, NB=2 ------------------
__device__ __forceinline__ uint32_t f2tf32(float v) {
  uint32_t r; asm("cvt.rna.tf32.f32 %0, %1;" : "=r"(r) : "f"(v));
  return r;
}

__device__ __forceinline__ void mma_tf32(float (&d)[4],
                                         uint32_t a0, uint32_t a1,
                                         uint32_t a2, uint32_t a3,
                                         uint32_t b0, uint32_t b1) {
  asm volatile(
      "mma.sync.aligned.m16n8k8.row.col.f32.tf32.tf32.f32 "
      "{%0,%1,%2,%3}, {%4,%5,%6,%7}, {%8,%9}, {%0,%1,%2,%3};"
      : "+f"(d[0]), "+f"(d[1]), "+f"(d[2]), "+f"(d[3])
      : "r"(a0), "r"(a1), "r"(a2), "r"(a3), "r"(b0), "r"(b1));
}

__device__ __forceinline__ void cpasync16(uint32_t smem_addr, const void* g) {
  asm volatile("cp.async.cg.shared.global [%0], [%1], 16;"
               :: "r"(smem_addr), "l"(g));
}

#define WPAD 68      // W smem row stride (floats): (gID*68+tig)%32 all distinct
#define MPAD 17      // mask smem row stride (words)
#define NCOLS 224    // 2 b x 112 padded t
#define WBUF (128 * WPAD)

// dyn smem layout (floats): Wbuf[2][WBUF] | xs[1024] | maskS[224*MPAD] | norm2[224]
extern __shared__ float k1smem[];

__global__ __launch_bounds__(256) void k1_norms_tc(
    const float* __restrict__ x, const float* __restrict__ W,
    const float* __restrict__ bias) {
  float* Wbuf = k1smem;
  float* xs = k1smem + 2 * WBUF;
  uint32_t* maskS = (uint32_t*)(xs + 1024);
  float* norm2 = (float*)(maskS + NCOLS * MPAD);

  const int b0 = blockIdx.x * 2;
  const int tid = threadIdx.x;
  const int lane = tid & 31, wid = tid >> 5;
  const int warp_m = wid & 1;          // 2 m-warps (64 d each)
  const int warp_n = wid >> 1;         // 4 n-warps (56 cols each)
  const int gID = lane >> 2, tig = lane & 3;
  const int n0 = warp_n * 56;
  const int bsel = warp_n >> 1;        // this warp's batch for xs

  // ---- block init ----
  for (int i = tid; i < 1024; i += 256) {
    int bs = i >> 9, c = i & 511;
    xs[i] = __uint_as_float(f2tf32(2.0f * x[(b0 + bs) * Cn + c]));
  }
  for (int i = tid; i < NCOLS * NW; i += 256) {
    int col = i >> 4, w = i & 15;
    int bs = (col >= 112) ? 1 : 0;
    int t = col - bs * 112;
    maskS[col * MPAD + w] =
        (t < Tn) ? g_mask[(t * Bn + b0 + bs) * NW + w] : 0u;
  }
  if (tid < NCOLS) norm2[tid] = 0.0f;

  // ---- prologue: stage 0 ----
  {
    float* Wb = Wbuf;
    const float* Wg = W;  // mi=0, kc=0
#pragma unroll
    for (int r = 0; r < 8; r++) {
      int l = tid + r * 256;
      int d = l >> 4, c4 = (l & 15) << 2;
      cpasync16((uint32_t)__cvta_generic_to_shared(Wb + d * WPAD + c4),
                Wg + d * Cn + c4);
    }
    asm volatile("cp.async.commit_group;");
  }

  float acc[4][7][4];
#pragma unroll
  for (int mt = 0; mt < 4; mt++)
#pragma unroll
    for (int nt = 0; nt < 7; nt++)
#pragma unroll
      for (int r = 0; r < 4; r++) acc[mt][nt][r] = 0.0f;
  float ns0[7], ns1[7];
#pragma unroll
  for (int nt = 0; nt < 7; nt++) { ns0[nt] = 0.0f; ns1[nt] = 0.0f; }

#pragma unroll 1
  for (int s = 0; s < 32; s++) {
    const int kc = s & 7;
    // issue next stage
    if (s < 31) {
      int s1 = s + 1;
      float* Wb = Wbuf + (s1 & 1) * WBUF;
      const float* Wg = W + ((s1 >> 3) * 128) * Cn + (s1 & 7) * 64;
#pragma unroll
      for (int r = 0; r < 8; r++) {
        int l = tid + r * 256;
        int d = l >> 4, c4 = (l & 15) << 2;
        cpasync16((uint32_t)__cvta_generic_to_shared(Wb + d * WPAD + c4),
                  Wg + d * Cn + c4);
      }
      asm volatile("cp.async.commit_group;");
      asm volatile("cp.async.wait_group 1;");
    } else {
      asm volatile("cp.async.wait_group 0;");
    }
    __syncthreads();

    const float* Wb = Wbuf + (s & 1) * WBUF;
    // per-stage mask words (LDS, padded stride -> conflict-free)
    uint32_t mw0[7], mw1[7];
#pragma unroll
    for (int nt = 0; nt < 7; nt++) {
      int col = n0 + nt * 8 + gID;
      mw0[nt] = maskS[col * MPAD + kc * 2];
      mw1[nt] = maskS[col * MPAD + kc * 2 + 1];
    }

#pragma unroll
    for (int kt = 0; kt < 8; kt++) {
      const int cl = kt * 8 + tig;
      uint32_t xv0 = __float_as_uint(xs[bsel * 512 + kc * 64 + cl]);
      uint32_t xv1 = __float_as_uint(xs[bsel * 512 + kc * 64 + cl + 4]);
      const float* rp = Wb + (warp_m * 64 + gID) * WPAD + cl;
      uint32_t a[4][4];
#pragma unroll
      for (int mt = 0; mt < 4; mt++) {
        a[mt][0] = __float_as_uint(rp[(mt * 16) * WPAD]);
        a[mt][1] = __float_as_uint(rp[(mt * 16 + 8) * WPAD]);
        a[mt][2] = __float_as_uint(rp[(mt * 16) * WPAD + 4]);
        a[mt][3] = __float_as_uint(rp[(mt * 16 + 8) * WPAD + 4]);
      }
      const int bit = ((kt & 3) << 3) + tig;
#pragma unroll
      for (int nt = 0; nt < 7; nt++) {
        uint32_t w = (kt < 4) ? mw0[nt] : mw1[nt];
        uint32_t bf0 = ((w >> bit) & 1u) ? xv0 : 0u;
        uint32_t bf1 = ((w >> (bit + 4)) & 1u) ? xv1 : 0u;
        mma_tf32(acc[0][nt], a[0][0], a[0][1], a[0][2], a[0][3], bf0, bf1);
        mma_tf32(acc[1][nt], a[1][0], a[1][1], a[1][2], a[1][3], bf0, bf1);
        mma_tf32(acc[2][nt], a[2][0], a[2][1], a[2][2], a[2][3], bf0, bf1);
        mma_tf32(acc[3][nt], a[3][0], a[3][1], a[3][2], a[3][3], bf0, bf1);
      }
    }

    // mi epilogue: fold y = acc + bias into register norm partials, reset acc
    if (kc == 7) {
      const int mi = s >> 3;
      float blo[4], bhi[4];
#pragma unroll
      for (int mt = 0; mt < 4; mt++) {
        int dg = mi * 128 + warp_m * 64 + mt * 16 + gID;
        blo[mt] = bias[dg];
        bhi[mt] = bias[dg + 8];
      }
#pragma unroll
      for (int nt = 0; nt < 7; nt++) {
        float s0 = 0.0f, s1 = 0.0f;
#pragma unroll
        for (int mt = 0; mt < 4; mt++) {
          float y0 = acc[mt][nt][0] + blo[mt];
          float y1 = acc[mt][nt][1] + blo[mt];
          float y2 = acc[mt][nt][2] + bhi[mt];
          float y3 = acc[mt][nt][3] + bhi[mt];
          s0 += y0 * y0 + y2 * y2;
          s1 += y1 * y1 + y3 * y3;
          acc[mt][nt][0] = 0.0f; acc[mt][nt][1] = 0.0f;
          acc[mt][nt][2] = 0.0f; acc[mt][nt][3] = 0.0f;
        }
        ns0[nt] += s0;
        ns1[nt] += s1;
      }
    }
    __syncthreads();
  }

  // cross-gID reduce (lanes sharing tig), then one conflict-free smem atomic
#pragma unroll
  for (int nt = 0; nt < 7; nt++) {
#pragma unroll
    for (int off = 4; off < 32; off <<= 1) {
      ns0[nt] += __shfl_xor_sync(0xFFFFFFFFu, ns0[nt], off);
      ns1[nt] += __shfl_xor_sync(0xFFFFFFFFu, ns1[nt], off);
    }
  }
  if (lane < 4) {
#pragma unroll
    for (int nt = 0; nt < 7; nt++) {
      atomicAdd(&norm2[n0 + nt * 8 + 2 * tig], ns0[nt]);
      atomicAdd(&norm2[n0 + nt * 8 + 2 * tig + 1], ns1[nt]);
    }
  }
  __syncthreads();
  if (tid < NCOLS) {
    int bs = (tid >= 112) ? 1 : 0;
    int t = tid - bs * 112;
    if (t < Tn) g_invn[(b0 + bs) * Tn + t] = rsqrtf(norm2[tid]);
  }
}

// K2: u_b[c] = 2 x_bc * sum_t m_tbc / n_tb ;  sigma_b = sum_t 1/n_tb
__global__ void k2_u(const float* __restrict__ x) {
  __shared__ float invn_s[Tn];
  const int b = blockIdx.x, tid = threadIdx.x;  // 128 threads
  if (tid < Tn) invn_s[tid] = g_invn[b * Tn + tid];
  __syncthreads();
  if (tid == 0) {
    float s = 0.0f;
    for (int t = 0; t < Tn; t++) s += invn_s[t];
    g_sigma[b] = s;
  }
  for (int c = tid; c < Cn; c += 128) {
    int w = c >> 5, sh = c & 31;
    float s = 0.0f;
    for (int t = 0; t < Tn; t++)
      if ((g_mask[(t * Bn + b) * NW + w] >> sh) & 1u) s += invn_s[t];
    g_u[b * Cn + c] = 2.0f * x[b * Cn + c] * s;
  }
}

// K3: small GEMMs. MODE 0: S = u * W^T + sigma*bias  ([B,C]x[C,D])
//                  MODE 1: v = S * W                 ([B,D]x[D,C])
template <int MODE>
__global__ void k3_gemm(const float* __restrict__ Wm,
                        const float* __restrict__ bias) {
  __shared__ float As[64][65];
  __shared__ float Bs[64][65];
  const float* A = (MODE == 0) ? g_u : g_S;
  float* outp = (MODE == 0) ? g_S : g_v;
  const int n0 = blockIdx.x * 64, m0 = blockIdx.y * 64;
  const int tid = threadIdx.x;                // 256
  const int nq = tid & 15, mq = tid >> 4;
  float acc[4][4] = {};
  for (int k0 = 0; k0 < 512; k0 += 64) {
    __syncthreads();
    for (int l = tid; l < 4096; l += 256) {
      int mm = l >> 6, kk = l & 63;
      As[kk][mm] = A[(m0 + mm) * 512 + k0 + kk];
    }
    if (MODE == 0) {
      for (int l = tid; l < 4096; l += 256) {
        int nn = l >> 6, kk = l & 63;
        Bs[kk][nn] = Wm[(n0 + nn) * 512 + k0 + kk];
      }
    } else {
      for (int l = tid; l < 4096; l += 256) {
        int kk = l >> 6, nn = l & 63;
        Bs[kk][nn] = Wm[(k0 + kk) * 512 + n0 + nn];
      }
    }
    __syncthreads();
#pragma unroll 8
    for (int kk = 0; kk < 64; kk++) {
      float a[4], bb[4];
#pragma unroll
      for (int i = 0; i < 4; i++) { a[i] = As[kk][mq * 4 + i]; bb[i] = Bs[kk][nq * 4 + i]; }
#pragma unroll
      for (int i = 0; i < 4; i++)
#pragma unroll
        for (int j = 0; j < 4; j++) acc[i][j] = fmaf(a[i], bb[j], acc[i][j]);
    }
  }
#pragma unroll
  for (int i = 0; i < 4; i++) {
    int m = m0 + mq * 4 + i;
    float sg = (MODE == 0) ? g_sigma[m] : 0.0f;
#pragma unroll
    for (int j = 0; j < 4; j++) {
      int n = n0 + nq * 4 + j;
      float v = acc[i][j];
      if (MODE == 0) v += sg * bias[n];
      outp[m * 512 + n] = v;
    }
  }
}

// K3c: 1/|S_b| and b^T S_b
__global__ void k3c_reduce(const float* __restrict__ bias) {
  __shared__ float r1[128], r2[128];
  const int b = blockIdx.x, tid = threadIdx.x;  // 128
  float s1 = 0.0f, s2 = 0.0f;
  for (int d = tid; d < Dn; d += 128) {
    float v = g_S[b * Dn + d];
    s1 += v * v;
    s2 += bias[d] * v;
  }
  r1[tid] = s1; r2[tid] = s2;
  __syncthreads();
  for (int o = 64; o > 0; o >>= 1) {
    if (tid < o) { r1[tid] += r1[tid + o]; r2[tid] += r2[tid + o]; }
    __syncthreads();
  }
  if (tid == 0) { g_sinv[b] = rsqrtf(r1[0]); g_c0[b] = r2[0]; }
}

// K4: score_tb = (2 sum_c m*x*v + c0) * invn * sinv ; out = std over t (ddof=0)
__global__ void k4_scores(const float* __restrict__ x, float* __restrict__ out) {
  __shared__ float xv[Cn];
  __shared__ float sc[Tn];
  const int b = blockIdx.x, tid = threadIdx.x;  // 128
  for (int c = tid; c < Cn; c += 128)
    xv[c] = 2.0f * x[b * Cn + c] * g_v[b * Cn + c];
  __syncthreads();
  if (tid < Tn) {
    const int t = tid;
    const uint32_t* mw = &g_mask[(t * Bn + b) * NW];
    float s = 0.0f;
#pragma unroll
    for (int w = 0; w < NW; w++) {
      uint32_t m = mw[w];
      int base = w * 32;
#pragma unroll
      for (int k = 0; k < 32; k++)
        if (m & (1u << k)) s += xv[base + k];
    }
    sc[t] = (s + g_c0[b]) * g_invn[b * Tn + t] * g_sinv[b];
  }
  __syncthreads();
  if (tid == 0) {
    float m = 0.0f;
    for (int t = 0; t < Tn; t++) m += sc[t];
    m *= (1.0f / Tn);
    float v = 0.0f;
    for (int t = 0; t < Tn; t++) { float d = sc[t] - m; v += d * d; }
    v *= (1.0f / Tn);
    out[b] = sqrtf(v);
  }
}

#define K1_SMEM_BYTES ((2 * WBUF + 1024 + 0) * 4 + NCOLS * MPAD * 4 + NCOLS * 4)

extern "C" void kernel_launch(void* const* d_in, const int* in_sizes, int n_in,
                              void* d_out, int out_size) {
  const float* x    = (const float*)d_in[0];
  const float* W    = (const float*)d_in[1];
  const float* bias = (const float*)d_in[2];
  float* out = (float*)d_out;

  cudaFuncSetAttribute(k1_norms_tc,
                       cudaFuncAttributeMaxDynamicSharedMemorySize,
                       K1_SMEM_BYTES);

  k0_masks<<<819200, 256>>>();                // Tn*Bn*Cn / 256 elements
  k1_norms_tc<<<Bn / 2, 256, K1_SMEM_BYTES>>>(x, W, bias);
  k2_u<<<Bn, 128>>>(x);
  k3_gemm<0><<<dim3(8, 64), 256>>>(W, bias);  // S
  k3c_reduce<<<Bn, 128>>>(bias);              // |S|, b^T S
  k3_gemm<1><<<dim3(8, 64), 256>>>(W, bias);  // v = W^T S
  k4_scores<<<Bn, 128>>>(x, out);
}

// round 5
// speedup vs baseline: 6.4733x; 1.0121x over previous
#include <cuda_runtime.h>
#include <cstdint>

// Problem constants (fixed shapes)
#define Tn 100
#define Bn 4096
#define Cn 512
#define Dn 512
#define NW 16                    // 512 bits / 32 = mask words per (t,b)

// ---------------- scratch (static device globals; no allocation) ------------
__device__ uint32_t g_mask[Tn*Bn*NW];   // 26.2 MB packed dropout masks
__device__ float    g_Wtf[Dn*Cn];       // W pre-rounded to tf32 (rna)
__device__ float    g_invn[Bn*Tn];      // 1/|y_tb|
__device__ float    g_u[Bn*Cn];         // u_b[c] = 2 x_bc * sum_t m/n
__device__ float    g_sigma[Bn];        // sum_t 1/n
__device__ float    g_S[Bn*Dn];         // sum_t f_t  (unnormalized mean dir)
__device__ float    g_v[Bn*Cn];         // v_b = W^T S_b
__device__ float    g_sinv[Bn];         // 1/|S_b|
__device__ float    g_c0[Bn];           // b^T S_b

// ---------------- threefry2x32 (JAX-exact, key = (0, 42)) -------------------
__device__ __forceinline__ void tf_round4(uint32_t& x0, uint32_t& x1,
                                          int a, int b, int c, int d) {
  x0 += x1; x1 = __funnelshift_l(x1, x1, a); x1 ^= x0;
  x0 += x1; x1 = __funnelshift_l(x1, x1, b); x1 ^= x0;
  x0 += x1; x1 = __funnelshift_l(x1, x1, c); x1 ^= x0;
  x0 += x1; x1 = __funnelshift_l(x1, x1, d); x1 ^= x0;
}

__device__ __forceinline__ uint2 threefry2x32(uint32_t x0, uint32_t x1) {
  const uint32_t k0 = 0u, k1 = 42u;
  const uint32_t k2 = k0 ^ k1 ^ 0x1BD11BDAu;
  x0 += k0; x1 += k1;
  tf_round4(x0, x1, 13, 15, 26, 6);   x0 += k1; x1 += k2 + 1u;
  tf_round4(x0, x1, 17, 29, 16, 24);  x0 += k2; x1 += k0 + 2u;
  tf_round4(x0, x1, 13, 15, 26, 6);   x0 += k0; x1 += k1 + 3u;
  tf_round4(x0, x1, 17, 29, 16, 24);  x0 += k1; x1 += k2 + 4u;
  tf_round4(x0, x1, 13, 15, 26, 6);   x0 += k2; x1 += k0 + 5u;
  return make_uint2(x0, x1);
}

// K0: JAX threefry_partitionable 32-bit draws. bits(i) = out.x ^ out.y of
// threefry2x32(key=(0,42), ctr=(0, i)); keep <=> bit31 == 0.
__global__ void k0_masks() {
  uint32_t i = blockIdx.x * blockDim.x + threadIdx.x;   // element index
  uint2 o = threefry2x32(0u, i);
  uint32_t keep = (((o.x ^ o.y) >> 31) & 1u) ^ 1u;
  uint32_t word = __ballot_sync(0xFFFFFFFFu, keep != 0u);
  if ((threadIdx.x & 31u) == 0u) g_mask[i >> 5] = word;
}

__device__ __forceinline__ uint32_t f2tf32(float v) {
  uint32_t r; asm("cvt.rna.tf32.f32 %0, %1;" : "=r"(r) : "f"(v));
  return r;
}

// K0b: pre-round W to tf32 (rna) once.
__global__ void k0b_roundW(const float* __restrict__ W) {
  int i = blockIdx.x * blockDim.x + threadIdx.x;
  g_Wtf[i] = __uint_as_float(f2tf32(W[i]));
}

// ---------------- K1: tf32 tensor-core row-norm GEMM, NB=2 ------------------
__device__ __forceinline__ void mma_tf32(float (&d)[4],
                                         uint32_t a0, uint32_t a1,
                                         uint32_t a2, uint32_t a3,
                                         uint32_t b0, uint32_t b1) {
  asm volatile(
      "mma.sync.aligned.m16n8k8.row.col.f32.tf32.tf32.f32 "
      "{%0,%1,%2,%3}, {%4,%5,%6,%7}, {%8,%9}, {%0,%1,%2,%3};"
      : "+f"(d[0]), "+f"(d[1]), "+f"(d[2]), "+f"(d[3])
      : "r"(a0), "r"(a1), "r"(a2), "r"(a3), "r"(b0), "r"(b1));
}

__device__ __forceinline__ void cpasync16(uint32_t smem_addr, const void* g) {
  asm volatile("cp.async.cg.shared.global [%0], [%1], 16;"
               :: "r"(smem_addr), "l"(g));
}

#define WPAD 68      // W smem row stride (floats)
#define MPAD 17      // mask smem row stride (words)
#define NCOLS 224    // 2 b x 112 padded t
#define WBUF (128 * WPAD)

// dyn smem layout (floats): Wbuf[2][WBUF] | xs[1024] | maskS[224*MPAD] | norm2[224]
extern __shared__ float k1smem[];

__global__ __launch_bounds__(256) void k1_norms_tc(
    const float* __restrict__ x, const float* __restrict__ bias) {
  float* Wbuf = k1smem;
  float* xs = k1smem + 2 * WBUF;
  uint32_t* maskS = (uint32_t*)(xs + 1024);
  float* norm2 = (float*)(maskS + NCOLS * MPAD);
  const float* W = g_Wtf;

  const int b0 = blockIdx.x * 2;
  const int tid = threadIdx.x;
  const int lane = tid & 31, wid = tid >> 5;
  const int warp_m = wid & 1;          // 2 m-warps (64 d each)
  const int warp_n = wid >> 1;         // 4 n-warps (56 cols each)
  const int gID = lane >> 2, tig = lane & 3;
  const int n0 = warp_n * 56;
  const int bsel = warp_n >> 1;        // this warp's batch for xs

  // ---- block init ----
  for (int i = tid; i < 1024; i += 256) {
    int bs = i >> 9, c = i & 511;
    xs[i] = __uint_as_float(f2tf32(2.0f * x[(b0 + bs) * Cn + c]));
  }
  for (int i = tid; i < NCOLS * NW; i += 256) {
    int col = i >> 4, w = i & 15;
    int bs = (col >= 112) ? 1 : 0;
    int t = col - bs * 112;
    maskS[col * MPAD + w] =
        (t < Tn) ? g_mask[(t * Bn + b0 + bs) * NW + w] : 0u;
  }
  if (tid < NCOLS) norm2[tid] = 0.0f;

  // ---- prologue: stage 0 ----
  {
    float* Wb = Wbuf;
    const float* Wg = W;  // mi=0, kc=0
#pragma unroll
    for (int r = 0; r < 8; r++) {
      int l = tid + r * 256;
      int d = l >> 4, c4 = (l & 15) << 2;
      cpasync16((uint32_t)__cvta_generic_to_shared(Wb + d * WPAD + c4),
                Wg + d * Cn + c4);
    }
    asm volatile("cp.async.commit_group;");
  }

  float acc[4][7][4];
#pragma unroll
  for (int mt = 0; mt < 4; mt++)
#pragma unroll
    for (int nt = 0; nt < 7; nt++)
#pragma unroll
      for (int r = 0; r < 4; r++) acc[mt][nt][r] = 0.0f;
  float ns0[7], ns1[7];
#pragma unroll
  for (int nt = 0; nt < 7; nt++) { ns0[nt] = 0.0f; ns1[nt] = 0.0f; }

#pragma unroll 1
  for (int s = 0; s < 32; s++) {
    const int kc = s & 7;
    // issue next stage
    if (s < 31) {
      int s1 = s + 1;
      float* Wb = Wbuf + (s1 & 1) * WBUF;
      const float* Wg = W + ((s1 >> 3) * 128) * Cn + (s1 & 7) * 64;
#pragma unroll
      for (int r = 0; r < 8; r++) {
        int l = tid + r * 256;
        int d = l >> 4, c4 = (l & 15) << 2;
        cpasync16((uint32_t)__cvta_generic_to_shared(Wb + d * WPAD + c4),
                  Wg + d * Cn + c4);
      }
      asm volatile("cp.async.commit_group;");
      asm volatile("cp.async.wait_group 1;");
    } else {
      asm volatile("cp.async.wait_group 0;");
    }
    __syncthreads();

    const float* Wb = Wbuf + (s & 1) * WBUF;
    // per-stage mask words (LDS, padded stride -> conflict-free)
    uint32_t mw0[7], mw1[7];
#pragma unroll
    for (int nt = 0; nt < 7; nt++) {
      int col = n0 + nt * 8 + gID;
      mw0[nt] = maskS[col * MPAD + kc * 2];
      mw1[nt] = maskS[col * MPAD + kc * 2 + 1];
    }

#pragma unroll
    for (int kt = 0; kt < 8; kt++) {
      const int cl = kt * 8 + tig;
      uint32_t xv0 = __float_as_uint(xs[bsel * 512 + kc * 64 + cl]);
      uint32_t xv1 = __float_as_uint(xs[bsel * 512 + kc * 64 + cl + 4]);
      const float* rp = Wb + (warp_m * 64 + gID) * WPAD + cl;
      uint32_t a[4][4];
#pragma unroll
      for (int mt = 0; mt < 4; mt++) {
        a[mt][0] = __float_as_uint(rp[(mt * 16) * WPAD]);
        a[mt][1] = __float_as_uint(rp[(mt * 16 + 8) * WPAD]);
        a[mt][2] = __float_as_uint(rp[(mt * 16) * WPAD + 4]);
        a[mt][3] = __float_as_uint(rp[(mt * 16 + 8) * WPAD + 4]);
      }
      const int bit = ((kt & 3) << 3) + tig;
#pragma unroll
      for (int nt = 0; nt < 7; nt++) {
        uint32_t w = (kt < 4) ? mw0[nt] : mw1[nt];
        uint32_t bf0 = ((w >> bit) & 1u) ? xv0 : 0u;
        uint32_t bf1 = ((w >> (bit + 4)) & 1u) ? xv1 : 0u;
        mma_tf32(acc[0][nt], a[0][0], a[0][1], a[0][2], a[0][3], bf0, bf1);
        mma_tf32(acc[1][nt], a[1][0], a[1][1], a[1][2], a[1][3], bf0, bf1);
        mma_tf32(acc[2][nt], a[2][0], a[2][1], a[2][2], a[2][3], bf0, bf1);
        mma_tf32(acc[3][nt], a[3][0], a[3][1], a[3][2], a[3][3], bf0, bf1);
      }
    }

    // mi epilogue: fold y = acc + bias into register norm partials, reset acc
    if (kc == 7) {
      const int mi = s >> 3;
      float blo[4], bhi[4];
#pragma unroll
      for (int mt = 0; mt < 4; mt++) {
        int dg = mi * 128 + warp_m * 64 + mt * 16 + gID;
        blo[mt] = bias[dg];
        bhi[mt] = bias[dg + 8];
      }
#pragma unroll
      for (int nt = 0; nt < 7; nt++) {
        float s0 = 0.0f, s1 = 0.0f;
#pragma unroll
        for (int mt = 0; mt < 4; mt++) {
          float y0 = acc[mt][nt][0] + blo[mt];
          float y1 = acc[mt][nt][1] + blo[mt];
          float y2 = acc[mt][nt][2] + bhi[mt];
          float y3 = acc[mt][nt][3] + bhi[mt];
          s0 += y0 * y0 + y2 * y2;
          s1 += y1 * y1 + y3 * y3;
          acc[mt][nt][0] = 0.0f; acc[mt][nt][1] = 0.0f;
          acc[mt][nt][2] = 0.0f; acc[mt][nt][3] = 0.0f;
        }
        ns0[nt] += s0;
        ns1[nt] += s1;
      }
    }
    __syncthreads();
  }

  // cross-gID reduce (lanes sharing tig), then one conflict-free smem atomic
#pragma unroll
  for (int nt = 0; nt < 7; nt++) {
#pragma unroll
    for (int off = 4; off < 32; off <<= 1) {
      ns0[nt] += __shfl_xor_sync(0xFFFFFFFFu, ns0[nt], off);
      ns1[nt] += __shfl_xor_sync(0xFFFFFFFFu, ns1[nt], off);
    }
  }
  if (lane < 4) {
#pragma unroll
    for (int nt = 0; nt < 7; nt++) {
      atomicAdd(&norm2[n0 + nt * 8 + 2 * tig], ns0[nt]);
      atomicAdd(&norm2[n0 + nt * 8 + 2 * tig + 1], ns1[nt]);
    }
  }
  __syncthreads();
  // invn (overwrite norm2 slot with invn for the fused-K2 pass)
  if (tid < NCOLS) {
    int bs = (tid >= 112) ? 1 : 0;
    int t = tid - bs * 112;
    float iv = rsqrtf(norm2[tid]);
    norm2[tid] = iv;
    if (t < Tn) g_invn[(b0 + bs) * Tn + t] = iv;
  }
  __syncthreads();

  // ---- fused K2: sigma_b and u_b[c] = 2 x * sum_t m/n ----
  if (tid < 2) {
    float s = 0.0f;
    for (int t = 0; t < Tn; t++) s += norm2[tid * 112 + t];
    g_sigma[b0 + tid] = s;
  }
#pragma unroll
  for (int bs = 0; bs < 2; bs++) {
#pragma unroll
    for (int j = 0; j < 2; j++) {
      int c = tid + j * 256;
      int w = c >> 5, sh = c & 31;
      float s = 0.0f;
      for (int col = 0; col < 112; col++) {
        uint32_t mwv = maskS[(bs * 112 + col) * MPAD + w];
        if ((mwv >> sh) & 1u) s += norm2[bs * 112 + col];
      }
      g_u[(b0 + bs) * Cn + c] = 2.0f * x[(b0 + bs) * Cn + c] * s;
    }
  }
}

// K3: small GEMMs. MODE 0: S = u * W^T + sigma*bias  ([B,C]x[C,D])
//                  MODE 1: v = S * W                 ([B,D]x[D,C])
template <int MODE>
__global__ void k3_gemm(const float* __restrict__ Wm,
                        const float* __restrict__ bias) {
  __shared__ float As[64][68];
  __shared__ float Bs[64][68];
  const float* A = (MODE == 0) ? g_u : g_S;
  float* outp = (MODE == 0) ? g_S : g_v;
  const int n0 = blockIdx.x * 64, m0 = blockIdx.y * 64;
  const int tid = threadIdx.x;                // 256
  const int nq = tid & 15, mq = tid >> 4;
  float acc[4][4] = {};
  for (int k0 = 0; k0 < 512; k0 += 64) {
    __syncthreads();
    for (int l = tid; l < 4096; l += 256) {
      int mm = l >> 6, kk = l & 63;
      As[kk][mm] = A[(m0 + mm) * 512 + k0 + kk];
    }
    if (MODE == 0) {
      for (int l = tid; l < 4096; l += 256) {
        int nn = l >> 6, kk = l & 63;
        Bs[kk][nn] = Wm[(n0 + nn) * 512 + k0 + kk];
      }
    } else {
      for (int l = tid; l < 4096; l += 256) {
        int kk = l >> 6, nn = l & 63;
        Bs[kk][nn] = Wm[(k0 + kk) * 512 + n0 + nn];
      }
    }
    __syncthreads();
#pragma unroll 8
    for (int kk = 0; kk < 64; kk++) {
      float4 av = *reinterpret_cast<const float4*>(&As[kk][mq * 4]);
      float4 bv = *reinterpret_cast<const float4*>(&Bs[kk][nq * 4]);
      float a[4] = {av.x, av.y, av.z, av.w};
      float bb[4] = {bv.x, bv.y, bv.z, bv.w};
#pragma unroll
      for (int i = 0; i < 4; i++)
#pragma unroll
        for (int j = 0; j < 4; j++) acc[i][j] = fmaf(a[i], bb[j], acc[i][j]);
    }
  }
#pragma unroll
  for (int i = 0; i < 4; i++) {
    int m = m0 + mq * 4 + i;
    float sg = (MODE == 0) ? g_sigma[m] : 0.0f;
#pragma unroll
    for (int j = 0; j < 4; j++) {
      int n = n0 + nq * 4 + j;
      float v = acc[i][j];
      if (MODE == 0) v += sg * bias[n];
      outp[m * 512 + n] = v;
    }
  }
}

// K3c: 1/|S_b| and b^T S_b
__global__ void k3c_reduce(const float* __restrict__ bias) {
  __shared__ float r1[128], r2[128];
  const int b = blockIdx.x, tid = threadIdx.x;  // 128
  float s1 = 0.0f, s2 = 0.0f;
  for (int d = tid; d < Dn; d += 128) {
    float v = g_S[b * Dn + d];
    s1 += v * v;
    s2 += bias[d] * v;
  }
  r1[tid] = s1; r2[tid] = s2;
  __syncthreads();
  for (int o = 64; o > 0; o >>= 1) {
    if (tid < o) { r1[tid] += r1[tid + o]; r2[tid] += r2[tid + o]; }
    __syncthreads();
  }
  if (tid == 0) { g_sinv[b] = rsqrtf(r1[0]); g_c0[b] = r2[0]; }
}

// K4: score_tb = (2 sum_c m*x*v + c0) * invn * sinv ; out = std over t (ddof=0)
__global__ void k4_scores(const float* __restrict__ x, float* __restrict__ out) {
  __shared__ float xv[Cn];
  __shared__ float sc[Tn];
  const int b = blockIdx.x, tid = threadIdx.x;  // 128
  for (int c = tid; c < Cn; c += 128)
    xv[c] = 2.0f * x[b * Cn + c] * g_v[b * Cn + c];
  __syncthreads();
  if (tid < Tn) {
    const int t = tid;
    const uint32_t* mw = &g_mask[(t * Bn + b) * NW];
    float s = 0.0f;
#pragma unroll
    for (int w = 0; w < NW; w++) {
      uint32_t m = mw[w];
      int base = w * 32;
#pragma unroll
      for (int k = 0; k < 32; k++)
        if (m & (1u << k)) s += xv[base + k];
    }
    sc[t] = (s + g_c0[b]) * g_invn[b * Tn + t] * g_sinv[b];
  }
  __syncthreads();
  if (tid == 0) {
    float m = 0.0f;
    for (int t = 0; t < Tn; t++) m += sc[t];
    m *= (1.0f / Tn);
    float v = 0.0f;
    for (int t = 0; t < Tn; t++) { float d = sc[t] - m; v += d * d; }
    v *= (1.0f / Tn);
    out[b] = sqrtf(v);
  }
}

#define K1_SMEM_BYTES ((2 * WBUF + 1024) * 4 + NCOLS * MPAD * 4 + NCOLS * 4)

extern "C" void kernel_launch(void* const* d_in, const int* in_sizes, int n_in,
                              void* d_out, int out_size) {
  const float* x    = (const float*)d_in[0];
  const float* W    = (const float*)d_in[1];
  const float* bias = (const float*)d_in[2];
  float* out = (float*)d_out;

  cudaFuncSetAttribute(k1_norms_tc,
                       cudaFuncAttributeMaxDynamicSharedMemorySize,
                       K1_SMEM_BYTES);

  k0_masks<<<819200, 256>>>();                // Tn*Bn*Cn / 256 elements
  k0b_roundW<<<1024, 256>>>(W);               // tf32-rna W once
  k1_norms_tc<<<Bn / 2, 256, K1_SMEM_BYTES>>>(x, bias);
  k3_gemm<0><<<dim3(8, 64), 256>>>(W, bias);  // S
  k3c_reduce<<<Bn, 128>>>(bias);              // |S|, b^T S
  k3_gemm<1><<<dim3(8, 64), 256>>>(W, bias);  // v = W^T S
  k4_scores<<<Bn, 128>>>(x, out);
}

// round 7
// speedup vs baseline: 8.3254x; 1.2861x over previous
#include <cuda_runtime.h>
#include <cuda_fp16.h>
#include <cstdint>

// Problem constants (fixed shapes)
#define Tn 100
#define Bn 4096
#define Cn 512
#define Dn 512
#define NW 16                    // 512 bits / 32 = mask words per (t,b)

// ---------------- scratch (static device globals; no allocation) ------------
__device__ uint32_t g_mask[Tn*Bn*NW];   // 26.2 MB packed dropout masks
__device__ __half   g_Wh[Dn*Cn];        // W pre-converted to fp16 (rn)
__device__ float    g_invn[Bn*Tn];      // 1/|y_tb|
__device__ float    g_u[Bn*Cn];         // u_b[c] = 2 x_bc * sum_t m/n
__device__ float    g_sigma[Bn];        // sum_t 1/n
__device__ float    g_S[Bn*Dn];         // sum_t f_t  (unnormalized mean dir)
__device__ float    g_v[Bn*Cn];         // v_b = W^T S_b
__device__ float    g_sinv[Bn];         // 1/|S_b|
__device__ float    g_c0[Bn];           // b^T S_b

// ---------------- threefry2x32 (JAX-exact, key = (0, 42)) -------------------
__device__ __forceinline__ void tf_round4(uint32_t& x0, uint32_t& x1,
                                          int a, int b, int c, int d) {
  x0 += x1; x1 = __funnelshift_l(x1, x1, a); x1 ^= x0;
  x0 += x1; x1 = __funnelshift_l(x1, x1, b); x1 ^= x0;
  x0 += x1; x1 = __funnelshift_l(x1, x1, c); x1 ^= x0;
  x0 += x1; x1 = __funnelshift_l(x1, x1, d); x1 ^= x0;
}

__device__ __forceinline__ uint2 threefry2x32(uint32_t x0, uint32_t x1) {
  const uint32_t k0 = 0u, k1 = 42u;
  const uint32_t k2 = k0 ^ k1 ^ 0x1BD11BDAu;
  x0 += k0; x1 += k1;
  tf_round4(x0, x1, 13, 15, 26, 6);   x0 += k1; x1 += k2 + 1u;
  tf_round4(x0, x1, 17, 29, 16, 24);  x0 += k2; x1 += k0 + 2u;
  tf_round4(x0, x1, 13, 15, 26, 6);   x0 += k0; x1 += k1 + 3u;
  tf_round4(x0, x1, 17, 29, 16, 24);  x0 += k1; x1 += k2 + 4u;
  tf_round4(x0, x1, 13, 15, 26, 6);   x0 += k2; x1 += k0 + 5u;
  return make_uint2(x0, x1);
}

// K0: JAX threefry_partitionable 32-bit draws. bits(i) = out.x ^ out.y of
// threefry2x32(key=(0,42), ctr=(0, i)); keep <=> bit31 == 0.
__global__ void k0_masks() {
  uint32_t i = blockIdx.x * blockDim.x + threadIdx.x;   // element index
  uint2 o = threefry2x32(0u, i);
  uint32_t keep = (((o.x ^ o.y) >> 31) & 1u) ^ 1u;
  uint32_t word = __ballot_sync(0xFFFFFFFFu, keep != 0u);
  if ((threadIdx.x & 31u) == 0u) g_mask[i >> 5] = word;
}

// K0b: pre-convert W to fp16 (rn) once.
__global__ void k0b_halfW(const float* __restrict__ W) {
  int i = blockIdx.x * blockDim.x + threadIdx.x;
  g_Wh[i] = __float2half(W[i]);
}

// ---------------- K1: fp16 tensor-core row-norm GEMM, NB=2 ------------------
__device__ __forceinline__ void mma_f16(float (&d)[4],
                                        uint32_t a0, uint32_t a1,
                                        uint32_t a2, uint32_t a3,
                                        uint32_t b0, uint32_t b1) {
  asm volatile(
      "mma.sync.aligned.m16n8k16.row.col.f32.f16.f16.f32 "
      "{%0,%1,%2,%3}, {%4,%5,%6,%7}, {%8,%9}, {%0,%1,%2,%3};"
      : "+f"(d[0]), "+f"(d[1]), "+f"(d[2]), "+f"(d[3])
      : "r"(a0), "r"(a1), "r"(a2), "r"(a3), "r"(b0), "r"(b1));
}

__device__ __forceinline__ void cpasync16(uint32_t smem_addr, const void* g) {
  asm volatile("cp.async.cg.shared.global [%0], [%1], 16;"
               :: "r"(smem_addr), "l"(g));
}

#define WPADH 72     // W smem row stride in halfs (byte stride 144)
#define MPAD 17      // mask smem row stride (words)
#define NCOLS 224    // 2 b x 112 padded t
#define WBUFH (128 * WPADH)   // halfs per W buffer

// dyn smem: Wbuf[2][WBUFH] halfs | xh[512] u32 | maskS[224*MPAD] u32 | norm2[224] f
extern __shared__ char k1smem[];

__global__ __launch_bounds__(256) void k1_norms_tc(
    const float* __restrict__ x, const float* __restrict__ bias) {
  __half* Wbuf = (__half*)k1smem;
  uint32_t* xh = (uint32_t*)(k1smem + 2 * WBUFH * 2);
  uint32_t* maskS = xh + 512;
  float* norm2 = (float*)(maskS + NCOLS * MPAD);

  const int b0 = blockIdx.x * 2;
  const int tid = threadIdx.x;
  const int lane = tid & 31, wid = tid >> 5;
  const int warp_m = wid & 1;          // 2 m-warps (64 d each)
  const int warp_n = wid >> 1;         // 4 n-warps (56 cols each)
  const int gID = lane >> 2, tig = lane & 3;
  const int n0 = warp_n * 56;
  const int bsel = warp_n >> 1;        // this warp's batch for xh

  // ---- block init ----
  for (int i = tid; i < 512; i += 256) {
    int bs = i >> 8, c2 = i & 255;
    float lo = 2.0f * x[(b0 + bs) * Cn + 2 * c2];
    float hi = 2.0f * x[(b0 + bs) * Cn + 2 * c2 + 1];
    __half2 h = __floats2half2_rn(lo, hi);
    xh[i] = *reinterpret_cast<uint32_t*>(&h);
  }
  for (int i = tid; i < NCOLS * NW; i += 256) {
    int col = i >> 4, w = i & 15;
    int bs = (col >= 112) ? 1 : 0;
    int t = col - bs * 112;
    maskS[col * MPAD + w] =
        (t < Tn) ? g_mask[(t * Bn + b0 + bs) * NW + w] : 0u;
  }
  if (tid < NCOLS) norm2[tid] = 0.0f;

  // ---- prologue: stage 0 ----
  {
    __half* Wb = Wbuf;
    const __half* Wg = g_Wh;  // mi=0, kc=0
#pragma unroll
    for (int r = 0; r < 4; r++) {
      int l = tid + r * 256;
      int d = l >> 3, ch = l & 7;
      cpasync16((uint32_t)__cvta_generic_to_shared(Wb + d * WPADH + ch * 8),
                Wg + d * Cn + ch * 8);
    }
    asm volatile("cp.async.commit_group;");
  }

  float acc[4][7][4];
#pragma unroll
  for (int mt = 0; mt < 4; mt++)
#pragma unroll
    for (int nt = 0; nt < 7; nt++)
#pragma unroll
      for (int r = 0; r < 4; r++) acc[mt][nt][r] = 0.0f;
  float ns0[7], ns1[7];
#pragma unroll
  for (int nt = 0; nt < 7; nt++) { ns0[nt] = 0.0f; ns1[nt] = 0.0f; }

#pragma unroll 1
  for (int s = 0; s < 32; s++) {
    const int kc = s & 7;
    // issue next stage
    if (s < 31) {
      int s1 = s + 1;
      __half* Wb = Wbuf + (s1 & 1) * WBUFH;
      const __half* Wg = g_Wh + ((s1 >> 3) * 128) * Cn + (s1 & 7) * 64;
#pragma unroll
      for (int r = 0; r < 4; r++) {
        int l = tid + r * 256;
        int d = l >> 3, ch = l & 7;
        cpasync16((uint32_t)__cvta_generic_to_shared(Wb + d * WPADH + ch * 8),
                  Wg + d * Cn + ch * 8);
      }
      asm volatile("cp.async.commit_group;");
      asm volatile("cp.async.wait_group 1;");
    } else {
      asm volatile("cp.async.wait_group 0;");
    }
    __syncthreads();

    const __half* Wb = Wbuf + (s & 1) * WBUFH;
    // per-stage mask words (LDS, padded stride -> conflict-free)
    uint32_t mw0[7], mw1[7];
#pragma unroll
    for (int nt = 0; nt < 7; nt++) {
      int col = n0 + nt * 8 + gID;
      mw0[nt] = maskS[col * MPAD + kc * 2];
      mw1[nt] = maskS[col * MPAD + kc * 2 + 1];
    }

#pragma unroll
    for (int kt = 0; kt < 4; kt++) {   // k16 tiles within 64-c chunk
      // x pairs (half2) for c = kc*64 + kt*16 + 2tig (+1), and +8,+9
      uint32_t xp0 = xh[bsel * 256 + kc * 32 + kt * 8 + tig];
      uint32_t xp1 = xh[bsel * 256 + kc * 32 + kt * 8 + tig + 4];
      // A fragments: rows warp_m*64 + mt*16 + gID (+8), cols kt*16+2tig (+8)
      const __half* rp = Wb + (warp_m * 64 + gID) * WPADH + kt * 16 + tig * 2;
      uint32_t a[4][4];
#pragma unroll
      for (int mt = 0; mt < 4; mt++) {
        a[mt][0] = *reinterpret_cast<const uint32_t*>(rp + (mt * 16) * WPADH);
        a[mt][1] = *reinterpret_cast<const uint32_t*>(rp + (mt * 16 + 8) * WPADH);
        a[mt][2] = *reinterpret_cast<const uint32_t*>(rp + (mt * 16) * WPADH + 8);
        a[mt][3] = *reinterpret_cast<const uint32_t*>(rp + (mt * 16 + 8) * WPADH + 8);
      }
      const int bit = ((kt & 1) << 4) + 2 * tig;
#pragma unroll
      for (int nt = 0; nt < 7; nt++) {
        uint32_t w = (kt < 2) ? mw0[nt] : mw1[nt];
        uint32_t sel0 = ((0u - ((w >> bit) & 1u)) & 0x0000FFFFu) |
                        ((0u - ((w >> (bit + 1)) & 1u)) & 0xFFFF0000u);
        uint32_t sel1 = ((0u - ((w >> (bit + 8)) & 1u)) & 0x0000FFFFu) |
                        ((0u - ((w >> (bit + 9)) & 1u)) & 0xFFFF0000u);
        uint32_t bf0 = xp0 & sel0;
        uint32_t bf1 = xp1 & sel1;
        mma_f16(acc[0][nt], a[0][0], a[0][1], a[0][2], a[0][3], bf0, bf1);
        mma_f16(acc[1][nt], a[1][0], a[1][1], a[1][2], a[1][3], bf0, bf1);
        mma_f16(acc[2][nt], a[2][0], a[2][1], a[2][2], a[2][3], bf0, bf1);
        mma_f16(acc[3][nt], a[3][0], a[3][1], a[3][2], a[3][3], bf0, bf1);
      }
    }

    // mi epilogue: fold y = acc + bias into register norm partials, reset acc
    if (kc == 7) {
      const int mi = s >> 3;
      float blo[4], bhi[4];
#pragma unroll
      for (int mt = 0; mt < 4; mt++) {
        int dg = mi * 128 + warp_m * 64 + mt * 16 + gID;
        blo[mt] = bias[dg];
        bhi[mt] = bias[dg + 8];
      }
#pragma unroll
      for (int nt = 0; nt < 7; nt++) {
        float s0 = 0.0f, s1 = 0.0f;
#pragma unroll
        for (int mt = 0; mt < 4; mt++) {
          float y0 = acc[mt][nt][0] + blo[mt];
          float y1 = acc[mt][nt][1] + blo[mt];
          float y2 = acc[mt][nt][2] + bhi[mt];
          float y3 = acc[mt][nt][3] + bhi[mt];
          s0 += y0 * y0 + y2 * y2;
          s1 += y1 * y1 + y3 * y3;
          acc[mt][nt][0] = 0.0f; acc[mt][nt][1] = 0.0f;
          acc[mt][nt][2] = 0.0f; acc[mt][nt][3] = 0.0f;
        }
        ns0[nt] += s0;
        ns1[nt] += s1;
      }
    }
    __syncthreads();
  }

  // cross-gID reduce (lanes sharing tig), then one conflict-free smem atomic
#pragma unroll
  for (int nt = 0; nt < 7; nt++) {
#pragma unroll
    for (int off = 4; off < 32; off <<= 1) {
      ns0[nt] += __shfl_xor_sync(0xFFFFFFFFu, ns0[nt], off);
      ns1[nt] += __shfl_xor_sync(0xFFFFFFFFu, ns1[nt], off);
    }
  }
  if (lane < 4) {
#pragma unroll
    for (int nt = 0; nt < 7; nt++) {
      atomicAdd(&norm2[n0 + nt * 8 + 2 * tig], ns0[nt]);
      atomicAdd(&norm2[n0 + nt * 8 + 2 * tig + 1], ns1[nt]);
    }
  }
  __syncthreads();
  // invn (overwrite norm2 slot with invn for the fused-K2 pass)
  if (tid < NCOLS) {
    int bs = (tid >= 112) ? 1 : 0;
    int t = tid - bs * 112;
    float iv = rsqrtf(norm2[tid]);
    norm2[tid] = iv;
    if (t < Tn) g_invn[(b0 + bs) * Tn + t] = iv;
  }
  __syncthreads();

  // ---- fused K2: sigma_b and u_b[c] = 2 x * sum_t m/n ----
  if (tid < 2) {
    float s = 0.0f;
    for (int t = 0; t < Tn; t++) s += norm2[tid * 112 + t];
    g_sigma[b0 + tid] = s;
  }
#pragma unroll
  for (int bs = 0; bs < 2; bs++) {
#pragma unroll
    for (int j = 0; j < 2; j++) {
      int c = tid + j * 256;
      int w = c >> 5, sh = c & 31;
      float s = 0.0f;
      for (int col = 0; col < 112; col++) {
        uint32_t mwv = maskS[(bs * 112 + col) * MPAD + w];
        if ((mwv >> sh) & 1u) s += norm2[bs * 112 + col];
      }
      g_u[(b0 + bs) * Cn + c] = 2.0f * x[(b0 + bs) * Cn + c] * s;
    }
  }
}

// K3: small GEMMs. MODE 0: S = u * W^T + sigma*bias  ([B,C]x[C,D])
//                  MODE 1: v = S * W                 ([B,D]x[D,C])
template <int MODE>
__global__ void k3_gemm(const float* __restrict__ Wm,
                        const float* __restrict__ bias) {
  __shared__ float As[64][68];
  __shared__ float Bs[64][68];
  const float* A = (MODE == 0) ? g_u : g_S;
  float* outp = (MODE == 0) ? g_S : g_v;
  const int n0 = blockIdx.x * 64, m0 = blockIdx.y * 64;
  const int tid = threadIdx.x;                // 256
  const int nq = tid & 15, mq = tid >> 4;
  float acc[4][4] = {};
  for (int k0 = 0; k0 < 512; k0 += 64) {
    __syncthreads();
    for (int l = tid; l < 4096; l += 256) {
      int mm = l >> 6, kk = l & 63;
      As[kk][mm] = A[(m0 + mm) * 512 + k0 + kk];
    }
    if (MODE == 0) {
      for (int l = tid; l < 4096; l += 256) {
        int nn = l >> 6, kk = l & 63;
        Bs[kk][nn] = Wm[(n0 + nn) * 512 + k0 + kk];
      }
    } else {
      for (int l = tid; l < 4096; l += 256) {
        int kk = l >> 6, nn = l & 63;
        Bs[kk][nn] = Wm[(k0 + kk) * 512 + n0 + nn];
      }
    }
    __syncthreads();
#pragma unroll 8
    for (int kk = 0; kk < 64; kk++) {
      float4 av = *reinterpret_cast<const float4*>(&As[kk][mq * 4]);
      float4 bv = *reinterpret_cast<const float4*>(&Bs[kk][nq * 4]);
      float a[4] = {av.x, av.y, av.z, av.w};
      float bb[4] = {bv.x, bv.y, bv.z, bv.w};
#pragma unroll
      for (int i = 0; i < 4; i++)
#pragma unroll
        for (int j = 0; j < 4; j++) acc[i][j] = fmaf(a[i], bb[j], acc[i][j]);
    }
  }
#pragma unroll
  for (int i = 0; i < 4; i++) {
    int m = m0 + mq * 4 + i;
    float sg = (MODE == 0) ? g_sigma[m] : 0.0f;
#pragma unroll
    for (int j = 0; j < 4; j++) {
      int n = n0 + nq * 4 + j;
      float v = acc[i][j];
      if (MODE == 0) v += sg * bias[n];
      outp[m * 512 + n] = v;
    }
  }
}

// K3c: 1/|S_b| and b^T S_b
__global__ void k3c_reduce(const float* __restrict__ bias) {
  __shared__ float r1[128], r2[128];
  const int b = blockIdx.x, tid = threadIdx.x;  // 128
  float s1 = 0.0f, s2 = 0.0f;
  for (int d = tid; d < Dn; d += 128) {
    float v = g_S[b * Dn + d];
    s1 += v * v;
    s2 += bias[d] * v;
  }
  r1[tid] = s1; r2[tid] = s2;
  __syncthreads();
  for (int o = 64; o > 0; o >>= 1) {
    if (tid < o) { r1[tid] += r1[tid + o]; r2[tid] += r2[tid + o]; }
    __syncthreads();
  }
  if (tid == 0) { g_sinv[b] = rsqrtf(r1[0]); g_c0[b] = r2[0]; }
}

// K4: score_tb = (2 sum_c m*x*v + c0) * invn * sinv ; out = std over t (ddof=0)
__global__ void k4_scores(const float* __restrict__ x, float* __restrict__ out) {
  __shared__ float xv[Cn];
  __shared__ float sc[Tn];
  const int b = blockIdx.x, tid = threadIdx.x;  // 128
  for (int c = tid; c < Cn; c += 128)
    xv[c] = 2.0f * x[b * Cn + c] * g_v[b * Cn + c];
  __syncthreads();
  if (tid < Tn) {
    const int t = tid;
    const uint32_t* mw = &g_mask[(t * Bn + b) * NW];
    float s = 0.0f;
#pragma unroll
    for (int w = 0; w < NW; w++) {
      uint32_t m = mw[w];
      int base = w * 32;
#pragma unroll
      for (int k = 0; k < 32; k++)
        if (m & (1u << k)) s += xv[base + k];
    }
    sc[t] = (s + g_c0[b]) * g_invn[b * Tn + t] * g_sinv[b];
  }
  __syncthreads();
  if (tid == 0) {
    float m = 0.0f;
    for (int t = 0; t < Tn; t++) m += sc[t];
    m *= (1.0f / Tn);
    float v = 0.0f;
    for (int t = 0; t < Tn; t++) { float d = sc[t] - m; v += d * d; }
    v *= (1.0f / Tn);
    out[b] = sqrtf(v);
  }
}

#define K1_SMEM_BYTES (2 * WBUFH * 2 + 512 * 4 + NCOLS * MPAD * 4 + NCOLS * 4)

extern "C" void kernel_launch(void* const* d_in, const int* in_sizes, int n_in,
                              void* d_out, int out_size) {
  const float* x    = (const float*)d_in[0];
  const float* W    = (const float*)d_in[1];
  const float* bias = (const float*)d_in[2];
  float* out = (float*)d_out;

  cudaFuncSetAttribute(k1_norms_tc,
                       cudaFuncAttributeMaxDynamicSharedMemorySize,
                       K1_SMEM_BYTES);

  k0_masks<<<819200, 256>>>();                // Tn*Bn*Cn / 256 elements
  k0b_halfW<<<1024, 256>>>(W);                // fp16 W once
  k1_norms_tc<<<Bn / 2, 256, K1_SMEM_BYTES>>>(x, bias);
  k3_gemm<0><<<dim3(8, 64), 256>>>(W, bias);  // S
  k3c_reduce<<<Bn, 128>>>(bias);              // |S|, b^T S
  k3_gemm<1><<<dim3(8, 64), 256>>>(W, bias);  // v = W^T S
  k4_scores<<<Bn, 128>>>(x, out);
}